// round 7
// baseline (speedup 1.0000x reference)
#include <cuda_runtime.h>

#define BNUM  32
#define TENC  4096
#define TPRED 1024
#define DHALF 512
#define DFULL 1024
#define NCLS  4
#define ENC_TS  32     // 4096 / 128
#define PRED_TS 8      // 1024 / 128
#define NSPLIT  (ENC_TS + PRED_TS)   // 40 CTAs per b
#define TCHUNK  128
#define LN_EPS 1e-5f

__device__ float g_part_e[ENC_TS  * BNUM * NCLS * DHALF];  // 8 MB
__device__ float g_part_p[PRED_TS * BNUM * NCLS * DHALF];  // 2 MB
__device__ float g_loss_b[BNUM];
__device__ unsigned int g_ticket_b[BNUM];
__device__ unsigned int g_ticket;

// ---------------------------------------------------------------------------
// Single fused kernel. grid (NSPLIT, BNUM), 128 threads, <=64 regs.
// Phase 1: masked partial sums via FFMA masks (16 FFMA / float4).
// Phase 2 (last CTA per b): smem-staged finisher (low register pressure).
// ---------------------------------------------------------------------------
__global__ void __launch_bounds__(128, 8)
fused_kernel(const float4* __restrict__ enc,
             const float4* __restrict__ pred,
             const int*    __restrict__ lab_e,
             const int*    __restrict__ lab_p,
             const int*    __restrict__ label,
             const float*  __restrict__ norm_w,
             const float*  __restrict__ norm_b,
             const float*  __restrict__ head_w,
             const float*  __restrict__ head_b,
             float*        __restrict__ out) {
    int ts  = blockIdx.x;
    int b   = blockIdx.y;
    int tid = threadIdx.x;
    int lane = tid & 31, wid = tid >> 5;   // 4 warps

    __shared__ __align__(16) float4 s_mask[TCHUNK];   // per-row class masks

    // ======================= Phase 1: masked partial sums ==================
    {
        const float4* x;
        const int*    lab;
        float4*       pp;
        int T, tsl;
        if (ts < ENC_TS) {
            x = enc;  lab = lab_e; pp = (float4*)g_part_e; T = TENC;  tsl = ts;
        } else {
            x = pred; lab = lab_p; pp = (float4*)g_part_p; T = TPRED; tsl = ts - ENC_TS;
        }
        int t0 = tsl * TCHUNK;

        {
            int c = lab[(size_t)b * T + t0 + tid];
            float4 m;
            m.x = (c == 0) ? 1.f : 0.f;
            m.y = (c == 1) ? 1.f : 0.f;
            m.z = (c == 2) ? 1.f : 0.f;
            m.w = (c == 3) ? 1.f : 0.f;
            s_mask[tid] = m;
        }
        __syncthreads();

        const float4* xp = x + ((size_t)b * T + t0) * (DHALF / 4) + tid;

        float4 a0 = {0.f,0.f,0.f,0.f};
        float4 a1 = {0.f,0.f,0.f,0.f};
        float4 a2 = {0.f,0.f,0.f,0.f};
        float4 a3 = {0.f,0.f,0.f,0.f};

        #pragma unroll 8
        for (int t = 0; t < TCHUNK; ++t) {
            float4 v = __ldcs(&xp[(size_t)t * (DHALF / 4)]);
            float4 m = s_mask[t];
            a0.x = fmaf(m.x, v.x, a0.x);  a0.y = fmaf(m.x, v.y, a0.y);
            a0.z = fmaf(m.x, v.z, a0.z);  a0.w = fmaf(m.x, v.w, a0.w);
            a1.x = fmaf(m.y, v.x, a1.x);  a1.y = fmaf(m.y, v.y, a1.y);
            a1.z = fmaf(m.y, v.z, a1.z);  a1.w = fmaf(m.y, v.w, a1.w);
            a2.x = fmaf(m.z, v.x, a2.x);  a2.y = fmaf(m.z, v.y, a2.y);
            a2.z = fmaf(m.z, v.z, a2.z);  a2.w = fmaf(m.z, v.w, a2.w);
            a3.x = fmaf(m.w, v.x, a3.x);  a3.y = fmaf(m.w, v.y, a3.y);
            a3.z = fmaf(m.w, v.z, a3.z);  a3.w = fmaf(m.w, v.w, a3.w);
        }

        size_t base = (((size_t)tsl * BNUM + b) * NCLS) * (DHALF / 4) + tid;
        pp[base + 0 * (DHALF / 4)] = a0;
        pp[base + 1 * (DHALF / 4)] = a1;
        pp[base + 2 * (DHALF / 4)] = a2;
        pp[base + 3 * (DHALF / 4)] = a3;
    }

    // ======================= ticket: last CTA per b ========================
    __threadfence();
    __syncthreads();
    __shared__ int s_win;
    if (tid == 0) {
        unsigned int t = atomicAdd(&g_ticket_b[b], 1u);
        s_win = (t == NSPLIT - 1);
        if (t == NSPLIT - 1) g_ticket_b[b] = 0;   // reset for next replay
    }
    __syncthreads();
    if (!s_win) return;
    __threadfence();                      // acquire partials

    // ======================= Phase 2: finisher for b =======================
    __shared__ __align__(16) float s_feat[NCLS][DFULL];   // 16 KB: class means
    __shared__ float s_inv[2][NCLS];
    __shared__ int   s_cw[2][4][NCLS];

    // ---- counts ----
    {
        int ce[NCLS] = {0,0,0,0}, cp[NCLS] = {0,0,0,0};
        for (int i = tid; i < TENC; i += 128) {
            int v = lab_e[(size_t)b * TENC + i];
            ce[0] += (v == 0); ce[1] += (v == 1); ce[2] += (v == 2); ce[3] += (v == 3);
        }
        for (int i = tid; i < TPRED; i += 128) {
            int v = lab_p[(size_t)b * TPRED + i];
            cp[0] += (v == 0); cp[1] += (v == 1); cp[2] += (v == 2); cp[3] += (v == 3);
        }
        #pragma unroll
        for (int k = 0; k < NCLS; ++k) {
            #pragma unroll
            for (int o = 16; o; o >>= 1) {
                ce[k] += __shfl_xor_sync(0xffffffffu, ce[k], o);
                cp[k] += __shfl_xor_sync(0xffffffffu, cp[k], o);
            }
            if (lane == 0) { s_cw[0][wid][k] = ce[k]; s_cw[1][wid][k] = cp[k]; }
        }
        __syncthreads();
        if (tid < 2 * NCLS) {
            int h = tid >> 2, k = tid & 3;
            int tot = s_cw[h][0][k] + s_cw[h][1][k] + s_cw[h][2][k] + s_cw[h][3][k];
            s_inv[h][k] = 1.f / fmaxf((float)tot, 1.f);
        }
        __syncthreads();
    }

    // ---- split-reduce into smem (sequential per class/half: low regs) ----
    {
        size_t stride = (size_t)BNUM * NCLS * (DHALF / 4);
        #pragma unroll
        for (int c = 0; c < NCLS; ++c) {
            size_t base = ((size_t)b * NCLS + c) * (DHALF / 4) + tid;
            float4 acc = {0.f,0.f,0.f,0.f};
            #pragma unroll 8
            for (int s = 0; s < ENC_TS; ++s) {
                float4 v = ((const float4*)g_part_e)[(size_t)s * stride + base];
                acc.x += v.x; acc.y += v.y; acc.z += v.z; acc.w += v.w;
            }
            float inv = s_inv[0][c];
            acc.x *= inv; acc.y *= inv; acc.z *= inv; acc.w *= inv;
            *(float4*)&s_feat[c][tid * 4] = acc;

            float4 accp = {0.f,0.f,0.f,0.f};
            #pragma unroll
            for (int s = 0; s < PRED_TS; ++s) {
                float4 v = ((const float4*)g_part_p)[(size_t)s * stride + base];
                accp.x += v.x; accp.y += v.y; accp.z += v.z; accp.w += v.w;
            }
            inv = s_inv[1][c];
            accp.x *= inv; accp.y *= inv; accp.z *= inv; accp.w *= inv;
            *(float4*)&s_feat[c][DHALF + tid * 4] = accp;
        }
    }
    __syncthreads();

    // ---- LayerNorm stats per class ----
    __shared__ float s_red[2 * NCLS][4];
    __shared__ float s_mu[NCLS], s_rstd[NCLS];
    #pragma unroll
    for (int c = 0; c < NCLS; ++c) {
        float4 e = *(const float4*)&s_feat[c][tid * 4];
        float4 p = *(const float4*)&s_feat[c][DHALF + tid * 4];
        float s = e.x + e.y + e.z + e.w + p.x + p.y + p.z + p.w;
        float q = e.x*e.x + e.y*e.y + e.z*e.z + e.w*e.w
                + p.x*p.x + p.y*p.y + p.z*p.z + p.w*p.w;
        #pragma unroll
        for (int o = 16; o; o >>= 1) {
            s += __shfl_xor_sync(0xffffffffu, s, o);
            q += __shfl_xor_sync(0xffffffffu, q, o);
        }
        if (lane == 0) { s_red[c * 2][wid] = s; s_red[c * 2 + 1][wid] = q; }
    }
    __syncthreads();
    if (tid < NCLS) {
        float s = s_red[tid*2][0] + s_red[tid*2][1] + s_red[tid*2][2] + s_red[tid*2][3];
        float q = s_red[tid*2+1][0] + s_red[tid*2+1][1] + s_red[tid*2+1][2] + s_red[tid*2+1][3];
        float mu  = s / (float)DFULL;
        float var = q / (float)DFULL - mu * mu;
        s_mu[tid]   = mu;
        s_rstd[tid] = rsqrtf(var + LN_EPS);
    }
    __syncthreads();

    // ---- logits (sequential per class: low regs) ----
    __shared__ float s_lg[4][NCLS][NCLS];
    __shared__ float s_logits[NCLS][NCLS];
    {
        int ge = tid * 4, gp = DHALF + tid * 4;
        #pragma unroll
        for (int c = 0; c < NCLS; ++c) {
            float mu = s_mu[c], r = s_rstd[c];
            float4 e = *(const float4*)&s_feat[c][ge];
            float4 p = *(const float4*)&s_feat[c][gp];
            float4 we = *(const float4*)(norm_w + ge);
            float4 wp = *(const float4*)(norm_w + gp);
            float4 be = *(const float4*)(norm_b + ge);
            float4 bp = *(const float4*)(norm_b + gp);
            float ex = (e.x - mu) * r * we.x + be.x;
            float ey = (e.y - mu) * r * we.y + be.y;
            float ez = (e.z - mu) * r * we.z + be.z;
            float ew = (e.w - mu) * r * we.w + be.w;
            float px = (p.x - mu) * r * wp.x + bp.x;
            float py = (p.y - mu) * r * wp.y + bp.y;
            float pz = (p.z - mu) * r * wp.z + bp.z;
            float pw = (p.w - mu) * r * wp.w + bp.w;
            #pragma unroll
            for (int n = 0; n < NCLS; ++n) {
                const float4 he = *(const float4*)(head_w + (size_t)n * DFULL + ge);
                const float4 hp = *(const float4*)(head_w + (size_t)n * DFULL + gp);
                float v = ex * he.x + ey * he.y + ez * he.z + ew * he.w
                        + px * hp.x + py * hp.y + pz * hp.z + pw * hp.w;
                #pragma unroll
                for (int o = 16; o; o >>= 1)
                    v += __shfl_xor_sync(0xffffffffu, v, o);
                if (lane == 0) s_lg[wid][c][n] = v;
            }
        }
    }
    __syncthreads();
    if (tid < NCLS * NCLS) {
        int c = tid >> 2, n = tid & 3;
        s_logits[c][n] = s_lg[0][c][n] + s_lg[1][c][n] + s_lg[2][c][n] + s_lg[3][c][n]
                       + head_b[n];
    }
    __syncthreads();

    // ---- per-b loss + final scalar ----
    if (tid == 0) {
        float sel_sum = 0.f;
        #pragma unroll
        for (int l = 0; l < NCLS; ++l) {
            int lb = label[b * NCLS + l];
            float m = s_logits[lb][0];
            #pragma unroll
            for (int n = 1; n < NCLS; ++n) m = fmaxf(m, s_logits[lb][n]);
            float se = 0.f;
            #pragma unroll
            for (int n = 0; n < NCLS; ++n) se += expf(s_logits[lb][n] - m);
            sel_sum += s_logits[lb][lb] - m - logf(se);
        }
        g_loss_b[b] = sel_sum;
        __threadfence();
        unsigned int t = atomicAdd(&g_ticket, 1u);
        if (t == BNUM - 1) {
            float tot = 0.f;
            #pragma unroll
            for (int i = 0; i < BNUM; ++i) tot += g_loss_b[i];
            out[0] = -tot / (float)(BNUM * NCLS);
            g_ticket = 0;   // reset for next replay
        }
    }
}

// ---------------------------------------------------------------------------
extern "C" void kernel_launch(void* const* d_in, const int* in_sizes, int n_in,
                              void* d_out, int out_size) {
    const float* enc_out = (const float*)d_in[0];
    const float* pred_out = (const float*)d_in[1];
    const int*   frame_label  = (const int*)d_in[2];
    const int*   frame_tlabel = (const int*)d_in[3];
    const int*   label  = (const int*)d_in[4];
    const float* norm_w = (const float*)d_in[5];
    const float* norm_b = (const float*)d_in[6];
    const float* head_w = (const float*)d_in[7];
    const float* head_b = (const float*)d_in[8];
    float* out = (float*)d_out;

    fused_kernel<<<dim3(NSPLIT, BNUM), 128>>>(
        (const float4*)enc_out, (const float4*)pred_out,
        frame_label, frame_tlabel, label,
        norm_w, norm_b, head_w, head_b, out);
}

// round 8
// speedup vs baseline: 1.0320x; 1.0320x over previous
#include <cuda_runtime.h>

#define BNUM  32
#define TENC  4096
#define TPRED 1024
#define DHALF 512
#define DFULL 1024
#define NCLS  4
#define ROWS_CTA 256            // rows per phase-1 CTA
#define ENC_TS  (TENC / ROWS_CTA)    // 16
#define PRED_TS (TPRED / ROWS_CTA)   // 4
#define NSPLIT  (ENC_TS + PRED_TS)   // 20 CTAs per b
#define LN_EPS 1e-5f

__device__ float g_part_e[ENC_TS  * BNUM * NCLS * DHALF];  // 4 MB
__device__ float g_part_p[PRED_TS * BNUM * NCLS * DHALF];  // 1 MB
__device__ float g_loss_b[BNUM];
__device__ unsigned int g_ticket;

// ---------------------------------------------------------------------------
// Phase 1: masked partial sums. grid (NSPLIT, BNUM), 128 threads, no reg cap.
// Proven select-form inner loop (R3 profile: ~6.2 TB/s). 256 rows per CTA.
// ---------------------------------------------------------------------------
__global__ void __launch_bounds__(128)
masked_sum_kernel(const float4* __restrict__ enc,
                  const float4* __restrict__ pred,
                  const int*    __restrict__ lab_e,
                  const int*    __restrict__ lab_p) {
    int ts  = blockIdx.x;
    int b   = blockIdx.y;
    int tid = threadIdx.x;

    const float4* x;
    const int*    lab;
    float4*       pp;
    int T, tsl;
    if (ts < ENC_TS) {
        x = enc;  lab = lab_e; pp = (float4*)g_part_e; T = TENC;  tsl = ts;
    } else {
        x = pred; lab = lab_p; pp = (float4*)g_part_p; T = TPRED; tsl = ts - ENC_TS;
    }
    int t0 = tsl * ROWS_CTA;

    __shared__ int slab[ROWS_CTA];
    slab[tid]       = lab[(size_t)b * T + t0 + tid];
    slab[tid + 128] = lab[(size_t)b * T + t0 + tid + 128];
    __syncthreads();

    const float4* xp = x + ((size_t)b * T + t0) * (DHALF / 4) + tid;

    float4 a0 = {0.f,0.f,0.f,0.f};
    float4 a1 = {0.f,0.f,0.f,0.f};
    float4 a2 = {0.f,0.f,0.f,0.f};
    float4 a3 = {0.f,0.f,0.f,0.f};

    #pragma unroll 8
    for (int t = 0; t < ROWS_CTA; ++t) {
        float4 v = __ldcs(&xp[(size_t)t * (DHALF / 4)]);
        int c = slab[t];
        a0.x += (c == 0) ? v.x : 0.f;  a0.y += (c == 0) ? v.y : 0.f;
        a0.z += (c == 0) ? v.z : 0.f;  a0.w += (c == 0) ? v.w : 0.f;
        a1.x += (c == 1) ? v.x : 0.f;  a1.y += (c == 1) ? v.y : 0.f;
        a1.z += (c == 1) ? v.z : 0.f;  a1.w += (c == 1) ? v.w : 0.f;
        a2.x += (c == 2) ? v.x : 0.f;  a2.y += (c == 2) ? v.y : 0.f;
        a2.z += (c == 2) ? v.z : 0.f;  a2.w += (c == 2) ? v.w : 0.f;
        a3.x += (c == 3) ? v.x : 0.f;  a3.y += (c == 3) ? v.y : 0.f;
        a3.z += (c == 3) ? v.z : 0.f;  a3.w += (c == 3) ? v.w : 0.f;
    }

    size_t base = (((size_t)tsl * BNUM + b) * NCLS) * (DHALF / 4) + tid;
    pp[base + 0 * (DHALF / 4)] = a0;
    pp[base + 1 * (DHALF / 4)] = a1;
    pp[base + 2 * (DHALF / 4)] = a2;
    pp[base + 3 * (DHALF / 4)] = a3;
}

// ---------------------------------------------------------------------------
// Tail: grid BNUM, 256 threads. Counts + split-reduce (high MLP) + LN +
// logits + per-b loss; global ticket writes the scalar.
// ---------------------------------------------------------------------------
__global__ void __launch_bounds__(256)
tail_kernel(const int*   __restrict__ lab_e,
            const int*   __restrict__ lab_p,
            const int*   __restrict__ label,
            const float* __restrict__ norm_w,
            const float* __restrict__ norm_b,
            const float* __restrict__ head_w,
            const float* __restrict__ head_b,
            float*       __restrict__ out) {
    int b    = blockIdx.x;
    int tid  = threadIdx.x;
    int lane = tid & 31;
    int wid  = tid >> 5;                // 0..7

    __shared__ __align__(16) float s_feat[NCLS][DFULL];   // 16 KB
    __shared__ float s_inv[2][NCLS];
    __shared__ int   s_cw[2][8][NCLS];

    // ---- counts (256 threads over both label arrays) ----
    {
        int ce[NCLS] = {0,0,0,0}, cp[NCLS] = {0,0,0,0};
        #pragma unroll 4
        for (int i = tid; i < TENC; i += 256) {
            int v = lab_e[(size_t)b * TENC + i];
            ce[0] += (v == 0); ce[1] += (v == 1); ce[2] += (v == 2); ce[3] += (v == 3);
        }
        #pragma unroll
        for (int i = tid; i < TPRED; i += 256) {
            int v = lab_p[(size_t)b * TPRED + i];
            cp[0] += (v == 0); cp[1] += (v == 1); cp[2] += (v == 2); cp[3] += (v == 3);
        }
        #pragma unroll
        for (int k = 0; k < NCLS; ++k) {
            #pragma unroll
            for (int o = 16; o; o >>= 1) {
                ce[k] += __shfl_xor_sync(0xffffffffu, ce[k], o);
                cp[k] += __shfl_xor_sync(0xffffffffu, cp[k], o);
            }
            if (lane == 0) { s_cw[0][wid][k] = ce[k]; s_cw[1][wid][k] = cp[k]; }
        }
        __syncthreads();
        if (tid < 2 * NCLS) {
            int h = tid >> 2, k = tid & 3;
            int tot = 0;
            #pragma unroll
            for (int w = 0; w < 8; ++w) tot += s_cw[h][w][k];
            s_inv[h][k] = 1.f / fmaxf((float)tot, 1.f);
        }
        __syncthreads();
    }

    // ---- split-reduce: threads 0..127 enc, 128..255 pred ----
    {
        size_t stride = (size_t)BNUM * NCLS * (DHALF / 4);
        if (tid < 128) {
            int d4 = tid;
            #pragma unroll
            for (int c = 0; c < NCLS; ++c) {
                size_t base = ((size_t)b * NCLS + c) * (DHALF / 4) + d4;
                float4 acc = {0.f,0.f,0.f,0.f};
                #pragma unroll
                for (int s = 0; s < ENC_TS; ++s) {
                    float4 v = ((const float4*)g_part_e)[(size_t)s * stride + base];
                    acc.x += v.x; acc.y += v.y; acc.z += v.z; acc.w += v.w;
                }
                float inv = s_inv[0][c];
                acc.x *= inv; acc.y *= inv; acc.z *= inv; acc.w *= inv;
                *(float4*)&s_feat[c][d4 * 4] = acc;
            }
        } else {
            int d4 = tid - 128;
            #pragma unroll
            for (int c = 0; c < NCLS; ++c) {
                size_t base = ((size_t)b * NCLS + c) * (DHALF / 4) + d4;
                float4 acc = {0.f,0.f,0.f,0.f};
                #pragma unroll
                for (int s = 0; s < PRED_TS; ++s) {
                    float4 v = ((const float4*)g_part_p)[(size_t)s * stride + base];
                    acc.x += v.x; acc.y += v.y; acc.z += v.z; acc.w += v.w;
                }
                float inv = s_inv[1][c];
                acc.x *= inv; acc.y *= inv; acc.z *= inv; acc.w *= inv;
                *(float4*)&s_feat[c][DHALF + d4 * 4] = acc;
            }
        }
    }
    __syncthreads();

    // ---- LayerNorm stats per class (256 threads, 8 warps) ----
    __shared__ float s_red[2 * NCLS][8];
    __shared__ float s_mu[NCLS], s_rstd[NCLS];
    int gd = tid * 4;
    float4 f[NCLS];
    #pragma unroll
    for (int c = 0; c < NCLS; ++c) {
        f[c] = *(const float4*)&s_feat[c][gd];
        float s = f[c].x + f[c].y + f[c].z + f[c].w;
        float q = f[c].x*f[c].x + f[c].y*f[c].y + f[c].z*f[c].z + f[c].w*f[c].w;
        #pragma unroll
        for (int o = 16; o; o >>= 1) {
            s += __shfl_xor_sync(0xffffffffu, s, o);
            q += __shfl_xor_sync(0xffffffffu, q, o);
        }
        if (lane == 0) { s_red[c * 2][wid] = s; s_red[c * 2 + 1][wid] = q; }
    }
    __syncthreads();
    if (tid < NCLS) {
        float s = 0.f, q = 0.f;
        #pragma unroll
        for (int w = 0; w < 8; ++w) { s += s_red[tid * 2][w]; q += s_red[tid * 2 + 1][w]; }
        float mu  = s / (float)DFULL;
        float var = q / (float)DFULL - mu * mu;
        s_mu[tid]   = mu;
        s_rstd[tid] = rsqrtf(var + LN_EPS);
    }
    __syncthreads();

    // ---- logits ----
    __shared__ float s_lg[8][NCLS][NCLS];
    __shared__ float s_logits[NCLS][NCLS];
    {
        float4 w4 = *(const float4*)(norm_w + gd);
        float4 b4 = *(const float4*)(norm_b + gd);
        float4 hw[NCLS];
        #pragma unroll
        for (int n = 0; n < NCLS; ++n)
            hw[n] = *(const float4*)(head_w + (size_t)n * DFULL + gd);

        #pragma unroll
        for (int c = 0; c < NCLS; ++c) {
            float mu = s_mu[c], r = s_rstd[c];
            float fx = (f[c].x - mu) * r * w4.x + b4.x;
            float fy = (f[c].y - mu) * r * w4.y + b4.y;
            float fz = (f[c].z - mu) * r * w4.z + b4.z;
            float fw = (f[c].w - mu) * r * w4.w + b4.w;
            #pragma unroll
            for (int n = 0; n < NCLS; ++n) {
                float v = fx * hw[n].x + fy * hw[n].y + fz * hw[n].z + fw * hw[n].w;
                #pragma unroll
                for (int o = 16; o; o >>= 1)
                    v += __shfl_xor_sync(0xffffffffu, v, o);
                if (lane == 0) s_lg[wid][c][n] = v;
            }
        }
    }
    __syncthreads();
    if (tid < NCLS * NCLS) {
        int c = tid >> 2, n = tid & 3;
        float v = 0.f;
        #pragma unroll
        for (int w = 0; w < 8; ++w) v += s_lg[w][c][n];
        s_logits[c][n] = v + head_b[n];
    }
    __syncthreads();

    // ---- per-b loss + global scalar ----
    if (tid == 0) {
        float sel_sum = 0.f;
        #pragma unroll
        for (int l = 0; l < NCLS; ++l) {
            int lb = label[b * NCLS + l];
            float m = s_logits[lb][0];
            #pragma unroll
            for (int n = 1; n < NCLS; ++n) m = fmaxf(m, s_logits[lb][n]);
            float se = 0.f;
            #pragma unroll
            for (int n = 0; n < NCLS; ++n) se += expf(s_logits[lb][n] - m);
            sel_sum += s_logits[lb][lb] - m - logf(se);
        }
        g_loss_b[b] = sel_sum;
        __threadfence();
        unsigned int t = atomicAdd(&g_ticket, 1u);
        if (t == BNUM - 1) {
            float tot = 0.f;
            #pragma unroll
            for (int i = 0; i < BNUM; ++i) tot += g_loss_b[i];
            out[0] = -tot / (float)(BNUM * NCLS);
            g_ticket = 0;   // reset for next replay
        }
    }
}

// ---------------------------------------------------------------------------
extern "C" void kernel_launch(void* const* d_in, const int* in_sizes, int n_in,
                              void* d_out, int out_size) {
    const float* enc_out = (const float*)d_in[0];
    const float* pred_out = (const float*)d_in[1];
    const int*   frame_label  = (const int*)d_in[2];
    const int*   frame_tlabel = (const int*)d_in[3];
    const int*   label  = (const int*)d_in[4];
    const float* norm_w = (const float*)d_in[5];
    const float* norm_b = (const float*)d_in[6];
    const float* head_w = (const float*)d_in[7];
    const float* head_b = (const float*)d_in[8];
    float* out = (float*)d_out;

    masked_sum_kernel<<<dim3(NSPLIT, BNUM), 128>>>(
        (const float4*)enc_out, (const float4*)pred_out,
        frame_label, frame_tlabel);

    tail_kernel<<<BNUM, 256>>>(frame_label, frame_tlabel, label,
                               norm_w, norm_b, head_w, head_b, out);
}

// round 9
// speedup vs baseline: 1.0537x; 1.0210x over previous
#include <cuda_runtime.h>

#define BNUM  32
#define TENC  4096
#define TPRED 1024
#define DHALF 512
#define DFULL 1024
#define NCLS  4
#define ENC_TS  32     // 4096 / 128
#define PRED_TS 8      // 1024 / 128
#define NSPLIT  (ENC_TS + PRED_TS)   // 40 CTAs per b
#define TCHUNK  128
#define LN_EPS 1e-5f

__device__ float g_part_e[ENC_TS  * BNUM * NCLS * DHALF];  // 8 MB
__device__ float g_part_p[PRED_TS * BNUM * NCLS * DHALF];  // 2 MB
__device__ float g_loss_b[BNUM];
__device__ unsigned int g_ticket_b[BNUM];
__device__ unsigned int g_ticket;

// ---------------------------------------------------------------------------
// Single fused kernel. grid (NSPLIT, BNUM), 128 threads.
// Phase 1: EXACT R3 streaming loop (select form, proven ~6.3 TB/s shape).
// Phase 2: last CTA per b (ticket) -> lean smem-staged finisher (unroll 4).
// ---------------------------------------------------------------------------
__global__ void __launch_bounds__(128)
fused_kernel(const float4* __restrict__ enc,
             const float4* __restrict__ pred,
             const int*    __restrict__ lab_e,
             const int*    __restrict__ lab_p,
             const int*    __restrict__ label,
             const float*  __restrict__ norm_w,
             const float*  __restrict__ norm_b,
             const float*  __restrict__ head_w,
             const float*  __restrict__ head_b,
             float*        __restrict__ out) {
    int ts  = blockIdx.x;
    int b   = blockIdx.y;
    int tid = threadIdx.x;
    int lane = tid & 31, wid = tid >> 5;   // 4 warps

    __shared__ int slab[TCHUNK];

    // ======================= Phase 1: masked partial sums (R3) =============
    {
        const float4* x;
        const int*    lab;
        float4*       pp;
        int T, tsl;
        if (ts < ENC_TS) {
            x = enc;  lab = lab_e; pp = (float4*)g_part_e; T = TENC;  tsl = ts;
        } else {
            x = pred; lab = lab_p; pp = (float4*)g_part_p; T = TPRED; tsl = ts - ENC_TS;
        }
        int t0 = tsl * TCHUNK;

        slab[tid] = lab[(size_t)b * T + t0 + tid];
        __syncthreads();

        const float4* xp = x + ((size_t)b * T + t0) * (DHALF / 4) + tid;

        float4 a0 = {0.f,0.f,0.f,0.f};
        float4 a1 = {0.f,0.f,0.f,0.f};
        float4 a2 = {0.f,0.f,0.f,0.f};
        float4 a3 = {0.f,0.f,0.f,0.f};

        #pragma unroll 8
        for (int t = 0; t < TCHUNK; ++t) {
            float4 v = __ldcs(&xp[(size_t)t * (DHALF / 4)]);
            int c = slab[t];
            a0.x += (c == 0) ? v.x : 0.f;  a0.y += (c == 0) ? v.y : 0.f;
            a0.z += (c == 0) ? v.z : 0.f;  a0.w += (c == 0) ? v.w : 0.f;
            a1.x += (c == 1) ? v.x : 0.f;  a1.y += (c == 1) ? v.y : 0.f;
            a1.z += (c == 1) ? v.z : 0.f;  a1.w += (c == 1) ? v.w : 0.f;
            a2.x += (c == 2) ? v.x : 0.f;  a2.y += (c == 2) ? v.y : 0.f;
            a2.z += (c == 2) ? v.z : 0.f;  a2.w += (c == 2) ? v.w : 0.f;
            a3.x += (c == 3) ? v.x : 0.f;  a3.y += (c == 3) ? v.y : 0.f;
            a3.z += (c == 3) ? v.z : 0.f;  a3.w += (c == 3) ? v.w : 0.f;
        }

        size_t base = (((size_t)tsl * BNUM + b) * NCLS) * (DHALF / 4) + tid;
        pp[base + 0 * (DHALF / 4)] = a0;
        pp[base + 1 * (DHALF / 4)] = a1;
        pp[base + 2 * (DHALF / 4)] = a2;
        pp[base + 3 * (DHALF / 4)] = a3;
    }

    // ======================= ticket: last CTA per b ========================
    __threadfence();
    __syncthreads();
    __shared__ int s_win;
    if (tid == 0) {
        unsigned int t = atomicAdd(&g_ticket_b[b], 1u);
        s_win = (t == NSPLIT - 1);
        if (t == NSPLIT - 1) g_ticket_b[b] = 0;   // reset for next replay
    }
    __syncthreads();
    if (!s_win) return;
    __threadfence();                      // acquire partials

    // ======================= Phase 2: lean finisher ========================
    __shared__ __align__(16) float s_feat[NCLS][DFULL];   // 16 KB: class means
    __shared__ float s_inv[2][NCLS];
    __shared__ int   s_cw[2][4][NCLS];

    // ---- counts ----
    {
        int ce[NCLS] = {0,0,0,0}, cp[NCLS] = {0,0,0,0};
        #pragma unroll 4
        for (int i = tid; i < TENC; i += 128) {
            int v = lab_e[(size_t)b * TENC + i];
            ce[0] += (v == 0); ce[1] += (v == 1); ce[2] += (v == 2); ce[3] += (v == 3);
        }
        #pragma unroll 4
        for (int i = tid; i < TPRED; i += 128) {
            int v = lab_p[(size_t)b * TPRED + i];
            cp[0] += (v == 0); cp[1] += (v == 1); cp[2] += (v == 2); cp[3] += (v == 3);
        }
        #pragma unroll
        for (int k = 0; k < NCLS; ++k) {
            #pragma unroll
            for (int o = 16; o; o >>= 1) {
                ce[k] += __shfl_xor_sync(0xffffffffu, ce[k], o);
                cp[k] += __shfl_xor_sync(0xffffffffu, cp[k], o);
            }
            if (lane == 0) { s_cw[0][wid][k] = ce[k]; s_cw[1][wid][k] = cp[k]; }
        }
        __syncthreads();
        if (tid < 2 * NCLS) {
            int h = tid >> 2, k = tid & 3;
            int tot = s_cw[h][0][k] + s_cw[h][1][k] + s_cw[h][2][k] + s_cw[h][3][k];
            s_inv[h][k] = 1.f / fmaxf((float)tot, 1.f);
        }
        __syncthreads();
    }

    // ---- split-reduce into smem (sequential per class, unroll 4) ----
    {
        size_t stride = (size_t)BNUM * NCLS * (DHALF / 4);
        #pragma unroll 1
        for (int c = 0; c < NCLS; ++c) {
            size_t base = ((size_t)b * NCLS + c) * (DHALF / 4) + tid;
            float4 acc = {0.f,0.f,0.f,0.f};
            #pragma unroll 4
            for (int s = 0; s < ENC_TS; ++s) {
                float4 v = ((const float4*)g_part_e)[(size_t)s * stride + base];
                acc.x += v.x; acc.y += v.y; acc.z += v.z; acc.w += v.w;
            }
            float inv = s_inv[0][c];
            acc.x *= inv; acc.y *= inv; acc.z *= inv; acc.w *= inv;
            *(float4*)&s_feat[c][tid * 4] = acc;

            float4 accp = {0.f,0.f,0.f,0.f};
            #pragma unroll 4
            for (int s = 0; s < PRED_TS; ++s) {
                float4 v = ((const float4*)g_part_p)[(size_t)s * stride + base];
                accp.x += v.x; accp.y += v.y; accp.z += v.z; accp.w += v.w;
            }
            inv = s_inv[1][c];
            accp.x *= inv; accp.y *= inv; accp.z *= inv; accp.w *= inv;
            *(float4*)&s_feat[c][DHALF + tid * 4] = accp;
        }
    }
    __syncthreads();

    // ---- LayerNorm stats per class ----
    __shared__ float s_red[2 * NCLS][4];
    __shared__ float s_mu[NCLS], s_rstd[NCLS];
    #pragma unroll 1
    for (int c = 0; c < NCLS; ++c) {
        float4 e = *(const float4*)&s_feat[c][tid * 4];
        float4 p = *(const float4*)&s_feat[c][DHALF + tid * 4];
        float s = e.x + e.y + e.z + e.w + p.x + p.y + p.z + p.w;
        float q = e.x*e.x + e.y*e.y + e.z*e.z + e.w*e.w
                + p.x*p.x + p.y*p.y + p.z*p.z + p.w*p.w;
        #pragma unroll
        for (int o = 16; o; o >>= 1) {
            s += __shfl_xor_sync(0xffffffffu, s, o);
            q += __shfl_xor_sync(0xffffffffu, q, o);
        }
        if (lane == 0) { s_red[c * 2][wid] = s; s_red[c * 2 + 1][wid] = q; }
    }
    __syncthreads();
    if (tid < NCLS) {
        float s = s_red[tid*2][0] + s_red[tid*2][1] + s_red[tid*2][2] + s_red[tid*2][3];
        float q = s_red[tid*2+1][0] + s_red[tid*2+1][1] + s_red[tid*2+1][2] + s_red[tid*2+1][3];
        float mu  = s / (float)DFULL;
        float var = q / (float)DFULL - mu * mu;
        s_mu[tid]   = mu;
        s_rstd[tid] = rsqrtf(var + LN_EPS);
    }
    __syncthreads();

    // ---- logits (sequential per class) ----
    __shared__ float s_lg[4][NCLS][NCLS];
    __shared__ float s_logits[NCLS][NCLS];
    {
        int ge = tid * 4, gp = DHALF + tid * 4;
        #pragma unroll 1
        for (int c = 0; c < NCLS; ++c) {
            float mu = s_mu[c], r = s_rstd[c];
            float4 e = *(const float4*)&s_feat[c][ge];
            float4 p = *(const float4*)&s_feat[c][gp];
            float4 we = *(const float4*)(norm_w + ge);
            float4 wp = *(const float4*)(norm_w + gp);
            float4 be = *(const float4*)(norm_b + ge);
            float4 bp = *(const float4*)(norm_b + gp);
            float ex = (e.x - mu) * r * we.x + be.x;
            float ey = (e.y - mu) * r * we.y + be.y;
            float ez = (e.z - mu) * r * we.z + be.z;
            float ew = (e.w - mu) * r * we.w + be.w;
            float px = (p.x - mu) * r * wp.x + bp.x;
            float py = (p.y - mu) * r * wp.y + bp.y;
            float pz = (p.z - mu) * r * wp.z + bp.z;
            float pw = (p.w - mu) * r * wp.w + bp.w;
            #pragma unroll
            for (int n = 0; n < NCLS; ++n) {
                const float4 he = *(const float4*)(head_w + (size_t)n * DFULL + ge);
                const float4 hp = *(const float4*)(head_w + (size_t)n * DFULL + gp);
                float v = ex * he.x + ey * he.y + ez * he.z + ew * he.w
                        + px * hp.x + py * hp.y + pz * hp.z + pw * hp.w;
                #pragma unroll
                for (int o = 16; o; o >>= 1)
                    v += __shfl_xor_sync(0xffffffffu, v, o);
                if (lane == 0) s_lg[wid][c][n] = v;
            }
        }
    }
    __syncthreads();
    if (tid < NCLS * NCLS) {
        int c = tid >> 2, n = tid & 3;
        s_logits[c][n] = s_lg[0][c][n] + s_lg[1][c][n] + s_lg[2][c][n] + s_lg[3][c][n]
                       + head_b[n];
    }
    __syncthreads();

    // ---- per-b loss + final scalar ----
    if (tid == 0) {
        float sel_sum = 0.f;
        #pragma unroll
        for (int l = 0; l < NCLS; ++l) {
            int lb = label[b * NCLS + l];
            float m = s_logits[lb][0];
            #pragma unroll
            for (int n = 1; n < NCLS; ++n) m = fmaxf(m, s_logits[lb][n]);
            float se = 0.f;
            #pragma unroll
            for (int n = 0; n < NCLS; ++n) se += expf(s_logits[lb][n] - m);
            sel_sum += s_logits[lb][lb] - m - logf(se);
        }
        g_loss_b[b] = sel_sum;
        __threadfence();
        unsigned int t = atomicAdd(&g_ticket, 1u);
        if (t == BNUM - 1) {
            float tot = 0.f;
            #pragma unroll
            for (int i = 0; i < BNUM; ++i) tot += g_loss_b[i];
            out[0] = -tot / (float)(BNUM * NCLS);
            g_ticket = 0;   // reset for next replay
        }
    }
}

// ---------------------------------------------------------------------------
extern "C" void kernel_launch(void* const* d_in, const int* in_sizes, int n_in,
                              void* d_out, int out_size) {
    const float* enc_out = (const float*)d_in[0];
    const float* pred_out = (const float*)d_in[1];
    const int*   frame_label  = (const int*)d_in[2];
    const int*   frame_tlabel = (const int*)d_in[3];
    const int*   label  = (const int*)d_in[4];
    const float* norm_w = (const float*)d_in[5];
    const float* norm_b = (const float*)d_in[6];
    const float* head_w = (const float*)d_in[7];
    const float* head_b = (const float*)d_in[8];
    float* out = (float*)d_out;

    fused_kernel<<<dim3(NSPLIT, BNUM), 128>>>(
        (const float4*)enc_out, (const float4*)pred_out,
        frame_label, frame_tlabel, label,
        norm_w, norm_b, head_w, head_b, out);
}

// round 10
// speedup vs baseline: 1.1810x; 1.1208x over previous
#include <cuda_runtime.h>

#define BNUM  32
#define TENC  4096
#define TPRED 1024
#define DHALF 512
#define DFULL 1024
#define NCLS  4
#define ENC_TS  32     // 4096 / 128
#define PRED_TS 8      // 1024 / 128
#define TCHUNK  128
#define LN_EPS 1e-5f

// Per-b raw sums (atomically accumulated). Zero-initialized at module load;
// tail kernel re-zeroes after consuming, so every graph replay starts clean.
__device__ float g_sum[BNUM * NCLS * DFULL];   // 512 KB
__device__ float g_loss_b[BNUM];
__device__ unsigned int g_ticket;

// ---------------------------------------------------------------------------
// Phase 1: masked sums. EXACT R3 streaming shape (grid 1280, 128 thr,
// select-form, no reg caps). Epilogue: REDG atomics into g_sum (no partials).
// ---------------------------------------------------------------------------
__global__ void __launch_bounds__(128)
masked_sum_kernel(const float4* __restrict__ enc,
                  const float4* __restrict__ pred,
                  const int*    __restrict__ lab_e,
                  const int*    __restrict__ lab_p) {
    int ts  = blockIdx.x;
    int b   = blockIdx.y;
    int tid = threadIdx.x;

    const float4* x;
    const int*    lab;
    int T, tsl, half_off;
    if (ts < ENC_TS) {
        x = enc;  lab = lab_e; T = TENC;  tsl = ts;           half_off = 0;
    } else {
        x = pred; lab = lab_p; T = TPRED; tsl = ts - ENC_TS;  half_off = DHALF;
    }
    int t0 = tsl * TCHUNK;

    __shared__ int slab[TCHUNK];
    slab[tid] = lab[(size_t)b * T + t0 + tid];
    __syncthreads();

    const float4* xp = x + ((size_t)b * T + t0) * (DHALF / 4) + tid;

    float4 a0 = {0.f,0.f,0.f,0.f};
    float4 a1 = {0.f,0.f,0.f,0.f};
    float4 a2 = {0.f,0.f,0.f,0.f};
    float4 a3 = {0.f,0.f,0.f,0.f};

    #pragma unroll 8
    for (int t = 0; t < TCHUNK; ++t) {
        float4 v = __ldcs(&xp[(size_t)t * (DHALF / 4)]);
        int c = slab[t];
        a0.x += (c == 0) ? v.x : 0.f;  a0.y += (c == 0) ? v.y : 0.f;
        a0.z += (c == 0) ? v.z : 0.f;  a0.w += (c == 0) ? v.w : 0.f;
        a1.x += (c == 1) ? v.x : 0.f;  a1.y += (c == 1) ? v.y : 0.f;
        a1.z += (c == 1) ? v.z : 0.f;  a1.w += (c == 1) ? v.w : 0.f;
        a2.x += (c == 2) ? v.x : 0.f;  a2.y += (c == 2) ? v.y : 0.f;
        a2.z += (c == 2) ? v.z : 0.f;  a2.w += (c == 2) ? v.w : 0.f;
        a3.x += (c == 3) ? v.x : 0.f;  a3.y += (c == 3) ? v.y : 0.f;
        a3.z += (c == 3) ? v.z : 0.f;  a3.w += (c == 3) ? v.w : 0.f;
    }

    // REDG.ADD epilogue: 16 no-return atomics per thread into g_sum[b][c][...]
    float* base = g_sum + ((size_t)b * NCLS) * DFULL + half_off + tid * 4;
    atomicAdd(base + 0*DFULL + 0, a0.x); atomicAdd(base + 0*DFULL + 1, a0.y);
    atomicAdd(base + 0*DFULL + 2, a0.z); atomicAdd(base + 0*DFULL + 3, a0.w);
    atomicAdd(base + 1*DFULL + 0, a1.x); atomicAdd(base + 1*DFULL + 1, a1.y);
    atomicAdd(base + 1*DFULL + 2, a1.z); atomicAdd(base + 1*DFULL + 3, a1.w);
    atomicAdd(base + 2*DFULL + 0, a2.x); atomicAdd(base + 2*DFULL + 1, a2.y);
    atomicAdd(base + 2*DFULL + 2, a2.z); atomicAdd(base + 2*DFULL + 3, a2.w);
    atomicAdd(base + 3*DFULL + 0, a3.x); atomicAdd(base + 3*DFULL + 1, a3.y);
    atomicAdd(base + 3*DFULL + 2, a3.z); atomicAdd(base + 3*DFULL + 3, a3.w);
}

// ---------------------------------------------------------------------------
// Tail: grid BNUM, 256 threads. Reads 16 KB of sums + labels, computes
// counts, LN, logits, loss; zeroes g_sum for the next replay; ticket scalar.
// ---------------------------------------------------------------------------
__global__ void __launch_bounds__(256)
tail_kernel(const int*   __restrict__ lab_e,
            const int*   __restrict__ lab_p,
            const int*   __restrict__ label,
            const float* __restrict__ norm_w,
            const float* __restrict__ norm_b,
            const float* __restrict__ head_w,
            const float* __restrict__ head_b,
            float*       __restrict__ out) {
    int b    = blockIdx.x;
    int tid  = threadIdx.x;
    int lane = tid & 31;
    int wid  = tid >> 5;                // 0..7

    __shared__ __align__(16) float s_feat[NCLS][DFULL];   // 16 KB
    __shared__ float s_inv[2][NCLS];
    __shared__ int   s_cw[2][8][NCLS];

    // ---- counts ----
    {
        int ce[NCLS] = {0,0,0,0}, cp[NCLS] = {0,0,0,0};
        #pragma unroll 4
        for (int i = tid; i < TENC; i += 256) {
            int v = lab_e[(size_t)b * TENC + i];
            ce[0] += (v == 0); ce[1] += (v == 1); ce[2] += (v == 2); ce[3] += (v == 3);
        }
        #pragma unroll
        for (int i = tid; i < TPRED; i += 256) {
            int v = lab_p[(size_t)b * TPRED + i];
            cp[0] += (v == 0); cp[1] += (v == 1); cp[2] += (v == 2); cp[3] += (v == 3);
        }
        #pragma unroll
        for (int k = 0; k < NCLS; ++k) {
            #pragma unroll
            for (int o = 16; o; o >>= 1) {
                ce[k] += __shfl_xor_sync(0xffffffffu, ce[k], o);
                cp[k] += __shfl_xor_sync(0xffffffffu, cp[k], o);
            }
            if (lane == 0) { s_cw[0][wid][k] = ce[k]; s_cw[1][wid][k] = cp[k]; }
        }
        __syncthreads();
        if (tid < 2 * NCLS) {
            int h = tid >> 2, k = tid & 3;
            int tot = 0;
            #pragma unroll
            for (int w = 0; w < 8; ++w) tot += s_cw[h][w][k];
            s_inv[h][k] = 1.f / fmaxf((float)tot, 1.f);
        }
        __syncthreads();
    }

    // ---- load sums -> means in smem; zero g_sum for next replay ----
    {
        int gd = tid * 4;                       // 0..1020
        int h  = (tid < 128) ? 0 : 1;           // which half for count divisor
        const float4 z = {0.f,0.f,0.f,0.f};
        #pragma unroll
        for (int c = 0; c < NCLS; ++c) {
            float4* p = (float4*)(g_sum + ((size_t)b * NCLS + c) * DFULL + gd);
            float4 v = *p;
            float inv = s_inv[h][c];
            v.x *= inv; v.y *= inv; v.z *= inv; v.w *= inv;
            *(float4*)&s_feat[c][gd] = v;
            *p = z;                             // reset accumulator
        }
    }
    __syncthreads();

    // ---- LayerNorm stats per class (256 threads, 8 warps) ----
    __shared__ float s_red[2 * NCLS][8];
    __shared__ float s_mu[NCLS], s_rstd[NCLS];
    int gd = tid * 4;
    float4 f[NCLS];
    #pragma unroll
    for (int c = 0; c < NCLS; ++c) {
        f[c] = *(const float4*)&s_feat[c][gd];
        float s = f[c].x + f[c].y + f[c].z + f[c].w;
        float q = f[c].x*f[c].x + f[c].y*f[c].y + f[c].z*f[c].z + f[c].w*f[c].w;
        #pragma unroll
        for (int o = 16; o; o >>= 1) {
            s += __shfl_xor_sync(0xffffffffu, s, o);
            q += __shfl_xor_sync(0xffffffffu, q, o);
        }
        if (lane == 0) { s_red[c * 2][wid] = s; s_red[c * 2 + 1][wid] = q; }
    }
    __syncthreads();
    if (tid < NCLS) {
        float s = 0.f, q = 0.f;
        #pragma unroll
        for (int w = 0; w < 8; ++w) { s += s_red[tid * 2][w]; q += s_red[tid * 2 + 1][w]; }
        float mu  = s / (float)DFULL;
        float var = q / (float)DFULL - mu * mu;
        s_mu[tid]   = mu;
        s_rstd[tid] = rsqrtf(var + LN_EPS);
    }
    __syncthreads();

    // ---- logits ----
    __shared__ float s_lg[8][NCLS][NCLS];
    __shared__ float s_logits[NCLS][NCLS];
    {
        float4 w4 = *(const float4*)(norm_w + gd);
        float4 b4 = *(const float4*)(norm_b + gd);
        float4 hw[NCLS];
        #pragma unroll
        for (int n = 0; n < NCLS; ++n)
            hw[n] = *(const float4*)(head_w + (size_t)n * DFULL + gd);

        #pragma unroll
        for (int c = 0; c < NCLS; ++c) {
            float mu = s_mu[c], r = s_rstd[c];
            float fx = (f[c].x - mu) * r * w4.x + b4.x;
            float fy = (f[c].y - mu) * r * w4.y + b4.y;
            float fz = (f[c].z - mu) * r * w4.z + b4.z;
            float fw = (f[c].w - mu) * r * w4.w + b4.w;
            #pragma unroll
            for (int n = 0; n < NCLS; ++n) {
                float v = fx * hw[n].x + fy * hw[n].y + fz * hw[n].z + fw * hw[n].w;
                #pragma unroll
                for (int o = 16; o; o >>= 1)
                    v += __shfl_xor_sync(0xffffffffu, v, o);
                if (lane == 0) s_lg[wid][c][n] = v;
            }
        }
    }
    __syncthreads();
    if (tid < NCLS * NCLS) {
        int c = tid >> 2, n = tid & 3;
        float v = 0.f;
        #pragma unroll
        for (int w = 0; w < 8; ++w) v += s_lg[w][c][n];
        s_logits[c][n] = v + head_b[n];
    }
    __syncthreads();

    // ---- per-b loss + global scalar ----
    if (tid == 0) {
        float sel_sum = 0.f;
        #pragma unroll
        for (int l = 0; l < NCLS; ++l) {
            int lb = label[b * NCLS + l];
            float m = s_logits[lb][0];
            #pragma unroll
            for (int n = 1; n < NCLS; ++n) m = fmaxf(m, s_logits[lb][n]);
            float se = 0.f;
            #pragma unroll
            for (int n = 0; n < NCLS; ++n) se += expf(s_logits[lb][n] - m);
            sel_sum += s_logits[lb][lb] - m - logf(se);
        }
        g_loss_b[b] = sel_sum;
        __threadfence();
        unsigned int t = atomicAdd(&g_ticket, 1u);
        if (t == BNUM - 1) {
            float tot = 0.f;
            #pragma unroll
            for (int i = 0; i < BNUM; ++i) tot += g_loss_b[i];
            out[0] = -tot / (float)(BNUM * NCLS);
            g_ticket = 0;   // reset for next replay
        }
    }
}

// ---------------------------------------------------------------------------
extern "C" void kernel_launch(void* const* d_in, const int* in_sizes, int n_in,
                              void* d_out, int out_size) {
    const float* enc_out = (const float*)d_in[0];
    const float* pred_out = (const float*)d_in[1];
    const int*   frame_label  = (const int*)d_in[2];
    const int*   frame_tlabel = (const int*)d_in[3];
    const int*   label  = (const int*)d_in[4];
    const float* norm_w = (const float*)d_in[5];
    const float* norm_b = (const float*)d_in[6];
    const float* head_w = (const float*)d_in[7];
    const float* head_b = (const float*)d_in[8];
    float* out = (float*)d_out;

    masked_sum_kernel<<<dim3(ENC_TS + PRED_TS, BNUM), 128>>>(
        (const float4*)enc_out, (const float4*)pred_out,
        frame_label, frame_tlabel);

    tail_kernel<<<BNUM, 256>>>(frame_label, frame_tlabel, label,
                               norm_w, norm_b, head_w, head_b, out);
}

// round 11
// speedup vs baseline: 1.2473x; 1.0561x over previous
#include <cuda_runtime.h>

#define BNUM  32
#define TENC  4096
#define TPRED 1024
#define DHALF 512
#define DFULL 1024
#define NCLS  4
#define ROWS_CTA 256
#define ENC_TS  (TENC / ROWS_CTA)    // 16
#define PRED_TS (TPRED / ROWS_CTA)   // 4
#define NSPLIT  (ENC_TS + PRED_TS)   // 20
#define LN_EPS 1e-5f

__device__ float g_part_e[ENC_TS  * BNUM * NCLS * DHALF];  // 4 MB
__device__ float g_part_p[PRED_TS * BNUM * NCLS * DHALF];  // 1 MB
__device__ unsigned int g_cnt[BNUM * 2 * NCLS];            // [b][half][cls]
__device__ float g_loss_b[BNUM];
__device__ unsigned int g_ticket;

// ---------------------------------------------------------------------------
// Phase 1: masked partial sums + inline counts.
// grid (NSPLIT, BNUM), 256 threads (8 warps): col = tid&127, row parity sub.
// Per-thread inner loop identical to R3 champion (128 strided LDG.128,
// 4 select-form float4 accumulators). Pair-combine via smem halves partials.
// ---------------------------------------------------------------------------
__global__ void __launch_bounds__(256)
masked_sum_kernel(const float4* __restrict__ enc,
                  const float4* __restrict__ pred,
                  const int*    __restrict__ lab_e,
                  const int*    __restrict__ lab_p) {
    int ts  = blockIdx.x;
    int b   = blockIdx.y;
    int tid = threadIdx.x;
    int col = tid & 127;
    int sub = tid >> 7;                // row parity

    const float4* x;
    const int*    lab;
    float4*       pp;
    int T, tsl, half;
    if (ts < ENC_TS) {
        x = enc;  lab = lab_e; pp = (float4*)g_part_e; T = TENC;  tsl = ts;          half = 0;
    } else {
        x = pred; lab = lab_p; pp = (float4*)g_part_p; T = TPRED; tsl = ts - ENC_TS; half = 1;
    }
    int t0 = tsl * ROWS_CTA;

    __shared__ int slab[ROWS_CTA];
    __shared__ int s_hist[NCLS];
    __shared__ __align__(16) float4 s_acc[NCLS][128];   // 8 KB pair-combine

    if (tid < NCLS) s_hist[tid] = 0;
    int myl = lab[(size_t)b * T + t0 + tid];
    slab[tid] = myl;
    __syncthreads();
    atomicAdd(&s_hist[myl], 1);

    const float4* xp = x + ((size_t)b * T + t0) * (DHALF / 4) + col;

    float4 a0 = {0.f,0.f,0.f,0.f};
    float4 a1 = {0.f,0.f,0.f,0.f};
    float4 a2 = {0.f,0.f,0.f,0.f};
    float4 a3 = {0.f,0.f,0.f,0.f};

    #pragma unroll 8
    for (int t = sub; t < ROWS_CTA; t += 2) {
        float4 v = __ldcs(&xp[(size_t)t * (DHALF / 4)]);
        int c = slab[t];
        a0.x += (c == 0) ? v.x : 0.f;  a0.y += (c == 0) ? v.y : 0.f;
        a0.z += (c == 0) ? v.z : 0.f;  a0.w += (c == 0) ? v.w : 0.f;
        a1.x += (c == 1) ? v.x : 0.f;  a1.y += (c == 1) ? v.y : 0.f;
        a1.z += (c == 1) ? v.z : 0.f;  a1.w += (c == 1) ? v.w : 0.f;
        a2.x += (c == 2) ? v.x : 0.f;  a2.y += (c == 2) ? v.y : 0.f;
        a2.z += (c == 2) ? v.z : 0.f;  a2.w += (c == 2) ? v.w : 0.f;
        a3.x += (c == 3) ? v.x : 0.f;  a3.y += (c == 3) ? v.y : 0.f;
        a3.z += (c == 3) ? v.z : 0.f;  a3.w += (c == 3) ? v.w : 0.f;
    }

    if (sub == 1) {
        s_acc[0][col] = a0; s_acc[1][col] = a1;
        s_acc[2][col] = a2; s_acc[3][col] = a3;
    }
    __syncthreads();
    if (sub == 0) {
        float4 v;
        v = s_acc[0][col]; a0.x += v.x; a0.y += v.y; a0.z += v.z; a0.w += v.w;
        v = s_acc[1][col]; a1.x += v.x; a1.y += v.y; a1.z += v.z; a1.w += v.w;
        v = s_acc[2][col]; a2.x += v.x; a2.y += v.y; a2.z += v.z; a2.w += v.w;
        v = s_acc[3][col]; a3.x += v.x; a3.y += v.y; a3.z += v.z; a3.w += v.w;

        size_t base = (((size_t)tsl * BNUM + b) * NCLS) * (DHALF / 4) + col;
        pp[base + 0 * (DHALF / 4)] = a0;
        pp[base + 1 * (DHALF / 4)] = a1;
        pp[base + 2 * (DHALF / 4)] = a2;
        pp[base + 3 * (DHALF / 4)] = a3;
    }
    if (tid < NCLS)
        atomicAdd(&g_cnt[(b * 2 + half) * NCLS + tid], (unsigned int)s_hist[tid]);
}

// ---------------------------------------------------------------------------
// Tail: grid BNUM, 256 threads. Reads counts (32 B) + 164 KB partials per b,
// LN + logits + loss; resets g_cnt; global ticket writes the scalar.
// ---------------------------------------------------------------------------
__global__ void __launch_bounds__(256)
tail_kernel(const int*   __restrict__ label,
            const float* __restrict__ norm_w,
            const float* __restrict__ norm_b,
            const float* __restrict__ head_w,
            const float* __restrict__ head_b,
            float*       __restrict__ out) {
    int b    = blockIdx.x;
    int tid  = threadIdx.x;
    int lane = tid & 31;
    int wid  = tid >> 5;                // 0..7

    __shared__ __align__(16) float s_feat[NCLS][DFULL];   // 16 KB
    __shared__ float s_inv[2][NCLS];

    // ---- counts from global accumulators ----
    if (tid < 2 * NCLS)
        s_inv[tid >> 2][tid & 3] =
            1.f / fmaxf((float)g_cnt[b * 2 * NCLS + tid], 1.f);
    __syncthreads();
    if (tid < 2 * NCLS) g_cnt[b * 2 * NCLS + tid] = 0;   // reset for replay

    // ---- split-reduce: threads 0..127 enc, 128..255 pred ----
    {
        size_t stride = (size_t)BNUM * NCLS * (DHALF / 4);
        int d4 = tid & 127;
        if (tid < 128) {
            #pragma unroll
            for (int c = 0; c < NCLS; ++c) {
                size_t base = ((size_t)b * NCLS + c) * (DHALF / 4) + d4;
                float4 acc = {0.f,0.f,0.f,0.f};
                #pragma unroll
                for (int s = 0; s < ENC_TS; ++s) {
                    float4 v = ((const float4*)g_part_e)[(size_t)s * stride + base];
                    acc.x += v.x; acc.y += v.y; acc.z += v.z; acc.w += v.w;
                }
                float inv = s_inv[0][c];
                acc.x *= inv; acc.y *= inv; acc.z *= inv; acc.w *= inv;
                *(float4*)&s_feat[c][d4 * 4] = acc;
            }
        } else {
            #pragma unroll
            for (int c = 0; c < NCLS; ++c) {
                size_t base = ((size_t)b * NCLS + c) * (DHALF / 4) + d4;
                float4 acc = {0.f,0.f,0.f,0.f};
                #pragma unroll
                for (int s = 0; s < PRED_TS; ++s) {
                    float4 v = ((const float4*)g_part_p)[(size_t)s * stride + base];
                    acc.x += v.x; acc.y += v.y; acc.z += v.z; acc.w += v.w;
                }
                float inv = s_inv[1][c];
                acc.x *= inv; acc.y *= inv; acc.z *= inv; acc.w *= inv;
                *(float4*)&s_feat[c][DHALF + d4 * 4] = acc;
            }
        }
    }
    __syncthreads();

    // ---- LayerNorm stats per class (256 threads, 8 warps) ----
    __shared__ float s_red[2 * NCLS][8];
    __shared__ float s_mu[NCLS], s_rstd[NCLS];
    int gd = tid * 4;
    float4 f[NCLS];
    #pragma unroll
    for (int c = 0; c < NCLS; ++c) {
        f[c] = *(const float4*)&s_feat[c][gd];
        float s = f[c].x + f[c].y + f[c].z + f[c].w;
        float q = f[c].x*f[c].x + f[c].y*f[c].y + f[c].z*f[c].z + f[c].w*f[c].w;
        #pragma unroll
        for (int o = 16; o; o >>= 1) {
            s += __shfl_xor_sync(0xffffffffu, s, o);
            q += __shfl_xor_sync(0xffffffffu, q, o);
        }
        if (lane == 0) { s_red[c * 2][wid] = s; s_red[c * 2 + 1][wid] = q; }
    }
    __syncthreads();
    if (tid < NCLS) {
        float s = 0.f, q = 0.f;
        #pragma unroll
        for (int w = 0; w < 8; ++w) { s += s_red[tid * 2][w]; q += s_red[tid * 2 + 1][w]; }
        float mu  = s / (float)DFULL;
        float var = q / (float)DFULL - mu * mu;
        s_mu[tid]   = mu;
        s_rstd[tid] = rsqrtf(var + LN_EPS);
    }
    __syncthreads();

    // ---- logits ----
    __shared__ float s_lg[8][NCLS][NCLS];
    __shared__ float s_logits[NCLS][NCLS];
    {
        float4 w4 = *(const float4*)(norm_w + gd);
        float4 b4 = *(const float4*)(norm_b + gd);
        float4 hw[NCLS];
        #pragma unroll
        for (int n = 0; n < NCLS; ++n)
            hw[n] = *(const float4*)(head_w + (size_t)n * DFULL + gd);

        #pragma unroll
        for (int c = 0; c < NCLS; ++c) {
            float mu = s_mu[c], r = s_rstd[c];
            float fx = (f[c].x - mu) * r * w4.x + b4.x;
            float fy = (f[c].y - mu) * r * w4.y + b4.y;
            float fz = (f[c].z - mu) * r * w4.z + b4.z;
            float fw = (f[c].w - mu) * r * w4.w + b4.w;
            #pragma unroll
            for (int n = 0; n < NCLS; ++n) {
                float v = fx * hw[n].x + fy * hw[n].y + fz * hw[n].z + fw * hw[n].w;
                #pragma unroll
                for (int o = 16; o; o >>= 1)
                    v += __shfl_xor_sync(0xffffffffu, v, o);
                if (lane == 0) s_lg[wid][c][n] = v;
            }
        }
    }
    __syncthreads();
    if (tid < NCLS * NCLS) {
        int c = tid >> 2, n = tid & 3;
        float v = 0.f;
        #pragma unroll
        for (int w = 0; w < 8; ++w) v += s_lg[w][c][n];
        s_logits[c][n] = v + head_b[n];
    }
    __syncthreads();

    // ---- per-b loss + global scalar ----
    if (tid == 0) {
        float sel_sum = 0.f;
        #pragma unroll
        for (int l = 0; l < NCLS; ++l) {
            int lb = label[b * NCLS + l];
            float m = s_logits[lb][0];
            #pragma unroll
            for (int n = 1; n < NCLS; ++n) m = fmaxf(m, s_logits[lb][n]);
            float se = 0.f;
            #pragma unroll
            for (int n = 0; n < NCLS; ++n) se += expf(s_logits[lb][n] - m);
            sel_sum += s_logits[lb][lb] - m - logf(se);
        }
        g_loss_b[b] = sel_sum;
        __threadfence();
        unsigned int t = atomicAdd(&g_ticket, 1u);
        if (t == BNUM - 1) {
            float tot = 0.f;
            #pragma unroll
            for (int i = 0; i < BNUM; ++i) tot += g_loss_b[i];
            out[0] = -tot / (float)(BNUM * NCLS);
            g_ticket = 0;   // reset for next replay
        }
    }
}

// ---------------------------------------------------------------------------
extern "C" void kernel_launch(void* const* d_in, const int* in_sizes, int n_in,
                              void* d_out, int out_size) {
    const float* enc_out = (const float*)d_in[0];
    const float* pred_out = (const float*)d_in[1];
    const int*   frame_label  = (const int*)d_in[2];
    const int*   frame_tlabel = (const int*)d_in[3];
    const int*   label  = (const int*)d_in[4];
    const float* norm_w = (const float*)d_in[5];
    const float* norm_b = (const float*)d_in[6];
    const float* head_w = (const float*)d_in[7];
    const float* head_b = (const float*)d_in[8];
    float* out = (float*)d_out;

    masked_sum_kernel<<<dim3(NSPLIT, BNUM), 256>>>(
        (const float4*)enc_out, (const float4*)pred_out,
        frame_label, frame_tlabel);

    tail_kernel<<<BNUM, 256>>>(label, norm_w, norm_b, head_w, head_b, out);
}

// round 13
// speedup vs baseline: 1.2516x; 1.0035x over previous
#include <cuda_runtime.h>

#define BNUM  32
#define TENC  4096
#define TPRED 1024
#define DHALF 512
#define DFULL 1024
#define NCLS  4
#define ROWS_CTA 256
#define ENC_TS  (TENC / ROWS_CTA)    // 16
#define PRED_TS (TPRED / ROWS_CTA)   // 4
#define NSPLIT  (ENC_TS + PRED_TS)   // 20
#define LN_EPS 1e-5f

__device__ float g_part_e[ENC_TS  * BNUM * NCLS * DHALF];  // 4 MB
__device__ float g_part_p[PRED_TS * BNUM * NCLS * DHALF];  // 1 MB
__device__ unsigned int g_cnt[BNUM * 2 * NCLS];            // [b][half][cls]
__device__ unsigned int g_ticket_b[BNUM];
__device__ float g_loss_b[BNUM];
__device__ unsigned int g_ticket;

// ---------------------------------------------------------------------------
// Producers: R11 streaming shape + early PDL trigger + per-b ticket publish.
// grid (NSPLIT, BNUM), 256 threads, parity pair-combine.
// ---------------------------------------------------------------------------
__global__ void __launch_bounds__(256)
masked_sum_kernel(const float4* __restrict__ enc,
                  const float4* __restrict__ pred,
                  const int*    __restrict__ lab_e,
                  const int*    __restrict__ lab_p) {
    // Let the dependent tail kernel launch while we stream.
    cudaTriggerProgrammaticLaunchCompletion();

    int ts  = blockIdx.x;
    int b   = blockIdx.y;
    int tid = threadIdx.x;
    int col = tid & 127;
    int sub = tid >> 7;                // row parity

    const float4* x;
    const int*    lab;
    float4*       pp;
    int T, tsl, half;
    if (ts < ENC_TS) {
        x = enc;  lab = lab_e; pp = (float4*)g_part_e; T = TENC;  tsl = ts;          half = 0;
    } else {
        x = pred; lab = lab_p; pp = (float4*)g_part_p; T = TPRED; tsl = ts - ENC_TS; half = 1;
    }
    int t0 = tsl * ROWS_CTA;

    __shared__ int slab[ROWS_CTA];
    __shared__ int s_hist[NCLS];
    __shared__ __align__(16) float4 s_acc[NCLS][128];   // 8 KB pair-combine

    if (tid < NCLS) s_hist[tid] = 0;
    int myl = lab[(size_t)b * T + t0 + tid];
    slab[tid] = myl;
    __syncthreads();
    atomicAdd(&s_hist[myl], 1);

    const float4* xp = x + ((size_t)b * T + t0) * (DHALF / 4) + col;

    float4 a0 = {0.f,0.f,0.f,0.f};
    float4 a1 = {0.f,0.f,0.f,0.f};
    float4 a2 = {0.f,0.f,0.f,0.f};
    float4 a3 = {0.f,0.f,0.f,0.f};

    #pragma unroll 8
    for (int t = sub; t < ROWS_CTA; t += 2) {
        float4 v = __ldcs(&xp[(size_t)t * (DHALF / 4)]);
        int c = slab[t];
        a0.x += (c == 0) ? v.x : 0.f;  a0.y += (c == 0) ? v.y : 0.f;
        a0.z += (c == 0) ? v.z : 0.f;  a0.w += (c == 0) ? v.w : 0.f;
        a1.x += (c == 1) ? v.x : 0.f;  a1.y += (c == 1) ? v.y : 0.f;
        a1.z += (c == 1) ? v.z : 0.f;  a1.w += (c == 1) ? v.w : 0.f;
        a2.x += (c == 2) ? v.x : 0.f;  a2.y += (c == 2) ? v.y : 0.f;
        a2.z += (c == 2) ? v.z : 0.f;  a2.w += (c == 2) ? v.w : 0.f;
        a3.x += (c == 3) ? v.x : 0.f;  a3.y += (c == 3) ? v.y : 0.f;
        a3.z += (c == 3) ? v.z : 0.f;  a3.w += (c == 3) ? v.w : 0.f;
    }

    if (sub == 1) {
        s_acc[0][col] = a0; s_acc[1][col] = a1;
        s_acc[2][col] = a2; s_acc[3][col] = a3;
    }
    __syncthreads();
    if (sub == 0) {
        float4 v;
        v = s_acc[0][col]; a0.x += v.x; a0.y += v.y; a0.z += v.z; a0.w += v.w;
        v = s_acc[1][col]; a1.x += v.x; a1.y += v.y; a1.z += v.z; a1.w += v.w;
        v = s_acc[2][col]; a2.x += v.x; a2.y += v.y; a2.z += v.z; a2.w += v.w;
        v = s_acc[3][col]; a3.x += v.x; a3.y += v.y; a3.z += v.z; a3.w += v.w;

        size_t base = (((size_t)tsl * BNUM + b) * NCLS) * (DHALF / 4) + col;
        pp[base + 0 * (DHALF / 4)] = a0;
        pp[base + 1 * (DHALF / 4)] = a1;
        pp[base + 2 * (DHALF / 4)] = a2;
        pp[base + 3 * (DHALF / 4)] = a3;
    }
    if (tid < NCLS)
        atomicAdd(&g_cnt[(b * 2 + half) * NCLS + tid], (unsigned int)s_hist[tid]);

    // publish: partials + counts visible, then bump per-b ticket
    __threadfence();
    __syncthreads();
    if (tid == 0)
        atomicAdd(&g_ticket_b[b], 1u);
}

// ---------------------------------------------------------------------------
// Tail (PDL secondary): grid BNUM, 256 threads. CTA b spin-waits for its 20
// producers, then reduces 164 KB (L2-hot) + LN + logits + loss.
// ---------------------------------------------------------------------------
__global__ void __launch_bounds__(256)
tail_kernel(const int*   __restrict__ label,
            const float* __restrict__ norm_w,
            const float* __restrict__ norm_b,
            const float* __restrict__ head_w,
            const float* __restrict__ head_b,
            float*       __restrict__ out) {
    int b    = blockIdx.x;
    int tid  = threadIdx.x;
    int lane = tid & 31;
    int wid  = tid >> 5;                // 0..7

    // ---- spin-wait for this b's producers ----
    if (tid == 0) {
        volatile unsigned int* t = &g_ticket_b[b];
        while (*t < NSPLIT) __nanosleep(128);
        *t = 0;                          // reset for next replay
    }
    __syncthreads();
    __threadfence();                     // acquire partials + counts

    __shared__ __align__(16) float s_feat[NCLS][DFULL];   // 16 KB
    __shared__ float s_inv[2][NCLS];

    if (tid < 2 * NCLS) {
        s_inv[tid >> 2][tid & 3] =
            1.f / fmaxf((float)g_cnt[b * 2 * NCLS + tid], 1.f);
        g_cnt[b * 2 * NCLS + tid] = 0;   // reset for replay
    }
    __syncthreads();

    // ---- split-reduce: threads 0..127 enc, 128..255 pred ----
    {
        size_t stride = (size_t)BNUM * NCLS * (DHALF / 4);
        int d4 = tid & 127;
        if (tid < 128) {
            #pragma unroll
            for (int c = 0; c < NCLS; ++c) {
                size_t base = ((size_t)b * NCLS + c) * (DHALF / 4) + d4;
                float4 acc = {0.f,0.f,0.f,0.f};
                #pragma unroll
                for (int s = 0; s < ENC_TS; ++s) {
                    float4 v = ((const float4*)g_part_e)[(size_t)s * stride + base];
                    acc.x += v.x; acc.y += v.y; acc.z += v.z; acc.w += v.w;
                }
                float inv = s_inv[0][c];
                acc.x *= inv; acc.y *= inv; acc.z *= inv; acc.w *= inv;
                *(float4*)&s_feat[c][d4 * 4] = acc;
            }
        } else {
            #pragma unroll
            for (int c = 0; c < NCLS; ++c) {
                size_t base = ((size_t)b * NCLS + c) * (DHALF / 4) + d4;
                float4 acc = {0.f,0.f,0.f,0.f};
                #pragma unroll
                for (int s = 0; s < PRED_TS; ++s) {
                    float4 v = ((const float4*)g_part_p)[(size_t)s * stride + base];
                    acc.x += v.x; acc.y += v.y; acc.z += v.z; acc.w += v.w;
                }
                float inv = s_inv[1][c];
                acc.x *= inv; acc.y *= inv; acc.z *= inv; acc.w *= inv;
                *(float4*)&s_feat[c][DHALF + d4 * 4] = acc;
            }
        }
    }
    __syncthreads();

    // ---- LayerNorm stats per class ----
    __shared__ float s_red[2 * NCLS][8];
    __shared__ float s_mu[NCLS], s_rstd[NCLS];
    int gd = tid * 4;
    float4 f[NCLS];
    #pragma unroll
    for (int c = 0; c < NCLS; ++c) {
        f[c] = *(const float4*)&s_feat[c][gd];
        float s = f[c].x + f[c].y + f[c].z + f[c].w;
        float q = f[c].x*f[c].x + f[c].y*f[c].y + f[c].z*f[c].z + f[c].w*f[c].w;
        #pragma unroll
        for (int o = 16; o; o >>= 1) {
            s += __shfl_xor_sync(0xffffffffu, s, o);
            q += __shfl_xor_sync(0xffffffffu, q, o);
        }
        if (lane == 0) { s_red[c * 2][wid] = s; s_red[c * 2 + 1][wid] = q; }
    }
    __syncthreads();
    if (tid < NCLS) {
        float s = 0.f, q = 0.f;
        #pragma unroll
        for (int w = 0; w < 8; ++w) { s += s_red[tid * 2][w]; q += s_red[tid * 2 + 1][w]; }
        float mu  = s / (float)DFULL;
        float var = q / (float)DFULL - mu * mu;
        s_mu[tid]   = mu;
        s_rstd[tid] = rsqrtf(var + LN_EPS);
    }
    __syncthreads();

    // ---- logits ----
    __shared__ float s_lg[8][NCLS][NCLS];
    __shared__ float s_logits[NCLS][NCLS];
    {
        float4 w4 = *(const float4*)(norm_w + gd);
        float4 b4 = *(const float4*)(norm_b + gd);
        float4 hw[NCLS];
        #pragma unroll
        for (int n = 0; n < NCLS; ++n)
            hw[n] = *(const float4*)(head_w + (size_t)n * DFULL + gd);

        #pragma unroll
        for (int c = 0; c < NCLS; ++c) {
            float mu = s_mu[c], r = s_rstd[c];
            float fx = (f[c].x - mu) * r * w4.x + b4.x;
            float fy = (f[c].y - mu) * r * w4.y + b4.y;
            float fz = (f[c].z - mu) * r * w4.z + b4.z;
            float fw = (f[c].w - mu) * r * w4.w + b4.w;
            #pragma unroll
            for (int n = 0; n < NCLS; ++n) {
                float v = fx * hw[n].x + fy * hw[n].y + fz * hw[n].z + fw * hw[n].w;
                #pragma unroll
                for (int o = 16; o; o >>= 1)
                    v += __shfl_xor_sync(0xffffffffu, v, o);
                if (lane == 0) s_lg[wid][c][n] = v;
            }
        }
    }
    __syncthreads();
    if (tid < NCLS * NCLS) {
        int c = tid >> 2, n = tid & 3;
        float v = 0.f;
        #pragma unroll
        for (int w = 0; w < 8; ++w) v += s_lg[w][c][n];
        s_logits[c][n] = v + head_b[n];
    }
    __syncthreads();

    // ---- per-b loss + global scalar ----
    if (tid == 0) {
        float sel_sum = 0.f;
        #pragma unroll
        for (int l = 0; l < NCLS; ++l) {
            int lb = label[b * NCLS + l];
            float m = s_logits[lb][0];
            #pragma unroll
            for (int n = 1; n < NCLS; ++n) m = fmaxf(m, s_logits[lb][n]);
            float se = 0.f;
            #pragma unroll
            for (int n = 0; n < NCLS; ++n) se += expf(s_logits[lb][n] - m);
            sel_sum += s_logits[lb][lb] - m - logf(se);
        }
        g_loss_b[b] = sel_sum;
        __threadfence();
        unsigned int t = atomicAdd(&g_ticket, 1u);
        if (t == BNUM - 1) {
            float tot = 0.f;
            #pragma unroll
            for (int i = 0; i < BNUM; ++i) tot += g_loss_b[i];
            out[0] = -tot / (float)(BNUM * NCLS);
            g_ticket = 0;   // reset for next replay
        }
    }
}

// ---------------------------------------------------------------------------
extern "C" void kernel_launch(void* const* d_in, const int* in_sizes, int n_in,
                              void* d_out, int out_size) {
    const float* enc_out = (const float*)d_in[0];
    const float* pred_out = (const float*)d_in[1];
    const int*   frame_label  = (const int*)d_in[2];
    const int*   frame_tlabel = (const int*)d_in[3];
    const int*   label  = (const int*)d_in[4];
    const float* norm_w = (const float*)d_in[5];
    const float* norm_b = (const float*)d_in[6];
    const float* head_w = (const float*)d_in[7];
    const float* head_b = (const float*)d_in[8];
    float* out = (float*)d_out;

    masked_sum_kernel<<<dim3(NSPLIT, BNUM), 256>>>(
        (const float4*)enc_out, (const float4*)pred_out,
        frame_label, frame_tlabel);

    // Tail as PDL secondary on the SAME (default) stream: it may launch as
    // soon as all producer CTAs hit their trigger; device-side tickets
    // provide the actual data dependency.
    {
        cudaLaunchConfig_t cfg = {};
        cfg.gridDim  = dim3(BNUM);
        cfg.blockDim = dim3(256);
        cfg.dynamicSmemBytes = 0;
        cfg.stream = 0;
        cudaLaunchAttribute attr[1];
        attr[0].id = cudaLaunchAttributeProgrammaticStreamSerialization;
        attr[0].val.programmaticStreamSerializationAllowed = 1;
        cfg.attrs = attr;
        cfg.numAttrs = 1;
        cudaLaunchKernelEx(&cfg, tail_kernel, label, norm_w, norm_b,
                           head_w, head_b, (float*)out);
    }
}